// round 2
// baseline (speedup 1.0000x reference)
#include <cuda_runtime.h>
#include <cstdint>

// Per-edge dot product: out[e] = dot(h[src[e]], h[dst[e]]), D=128 fp32.
// One warp per edge; each lane loads one float4 (16B) from each vector
// => 32 lanes * 16B = 512B = the full 128-float vector, coalesced.
//
// NOTE: reference is JAX with x64 disabled -> "int64" indices are actually
// int32 on device. Round-1 crash was reading them as long long.

__global__ void edge_dot_kernel(const float4* __restrict__ h,
                                const int* __restrict__ src,
                                const int* __restrict__ dst,
                                float* __restrict__ out,
                                int n_edges) {
    const int gwarp = (blockIdx.x * blockDim.x + threadIdx.x) >> 5;
    const int lane  = threadIdx.x & 31;
    if (gwarp >= n_edges) return;

    // Uniform across warp -> broadcast load
    const int s = __ldg(&src[gwarp]);
    const int d = __ldg(&dst[gwarp]);

    // Each node vector = 128 floats = 32 float4
    const float4 va = __ldg(&h[(long)s * 32 + lane]);
    const float4 vb = __ldg(&h[(long)d * 32 + lane]);

    float sum = va.x * vb.x;
    sum = fmaf(va.y, vb.y, sum);
    sum = fmaf(va.z, vb.z, sum);
    sum = fmaf(va.w, vb.w, sum);

    // Warp reduction
    #pragma unroll
    for (int off = 16; off > 0; off >>= 1)
        sum += __shfl_down_sync(0xFFFFFFFFu, sum, off);

    if (lane == 0) out[gwarp] = sum;
}

extern "C" void kernel_launch(void* const* d_in, const int* in_sizes, int n_in,
                              void* d_out, int out_size) {
    // Inputs: h [10000,128] f32, src [E] i32, dst [E] i32 (jax x64 disabled)
    const float4* h   = (const float4*)d_in[0];
    const int*    src = (const int*)d_in[1];
    const int*    dst = (const int*)d_in[2];
    float*        out = (float*)d_out;

    const int n_edges = in_sizes[1];          // E = 640000
    const int threads = 256;                  // 8 warps/block
    const int warps_per_block = threads / 32;
    const int blocks = (n_edges + warps_per_block - 1) / warps_per_block;

    edge_dot_kernel<<<blocks, threads>>>(h, src, dst, out, n_edges);
}

// round 3
// speedup vs baseline: 1.4517x; 1.4517x over previous
#include <cuda_runtime.h>
#include <cstdint>

// Per-edge dot: out[e] = dot(h[src[e]], h[dst[e]]), D=128 fp32.
// 4 edges per warp per iteration:
//  - int4 index loads (uniform broadcast, 1 wavefront each)
//  - 8 independent LDG.128 gathers per thread (4x MLP vs 1 edge/warp)
//  - butterfly reduce, lane 0 writes one float4 (STG.128) for 4 edges.

__device__ __forceinline__ float dot4(float4 a, float4 b) {
    float s = a.x * b.x;
    s = fmaf(a.y, b.y, s);
    s = fmaf(a.z, b.z, s);
    s = fmaf(a.w, b.w, s);
    return s;
}

__device__ __forceinline__ float warp_bfly_sum(float v) {
    #pragma unroll
    for (int off = 16; off > 0; off >>= 1)
        v += __shfl_xor_sync(0xFFFFFFFFu, v, off);
    return v;
}

__global__ void edge_dot4_kernel(const float4* __restrict__ h,
                                 const int4* __restrict__ src4,
                                 const int4* __restrict__ dst4,
                                 float4* __restrict__ out4,
                                 int n_groups) {
    const int g    = (blockIdx.x * blockDim.x + threadIdx.x) >> 5;
    const int lane = threadIdx.x & 31;
    if (g >= n_groups) return;

    // Uniform across warp: 4 src + 4 dst indices in two 16B loads
    const int4 s = __ldg(&src4[g]);
    const int4 d = __ldg(&dst4[g]);

    // 8 independent gathers (each warp-wide LDG.128 covers one 512B vector)
    const float4 a0 = __ldg(&h[(long)s.x * 32 + lane]);
    const float4 b0 = __ldg(&h[(long)d.x * 32 + lane]);
    const float4 a1 = __ldg(&h[(long)s.y * 32 + lane]);
    const float4 b1 = __ldg(&h[(long)d.y * 32 + lane]);
    const float4 a2 = __ldg(&h[(long)s.z * 32 + lane]);
    const float4 b2 = __ldg(&h[(long)d.z * 32 + lane]);
    const float4 a3 = __ldg(&h[(long)s.w * 32 + lane]);
    const float4 b3 = __ldg(&h[(long)d.w * 32 + lane]);

    float r0 = warp_bfly_sum(dot4(a0, b0));
    float r1 = warp_bfly_sum(dot4(a1, b1));
    float r2 = warp_bfly_sum(dot4(a2, b2));
    float r3 = warp_bfly_sum(dot4(a3, b3));

    if (lane == 0) out4[g] = make_float4(r0, r1, r2, r3);
}

// Tail: one warp per edge (only launched when n_edges % 4 != 0)
__global__ void edge_dot_tail_kernel(const float4* __restrict__ h,
                                     const int* __restrict__ src,
                                     const int* __restrict__ dst,
                                     float* __restrict__ out,
                                     int base, int n_edges) {
    const int e    = base + ((blockIdx.x * blockDim.x + threadIdx.x) >> 5);
    const int lane = threadIdx.x & 31;
    if (e >= n_edges) return;
    const int s = __ldg(&src[e]);
    const int d = __ldg(&dst[e]);
    const float4 va = __ldg(&h[(long)s * 32 + lane]);
    const float4 vb = __ldg(&h[(long)d * 32 + lane]);
    float r = warp_bfly_sum(dot4(va, vb));
    if (lane == 0) out[e] = r;
}

extern "C" void kernel_launch(void* const* d_in, const int* in_sizes, int n_in,
                              void* d_out, int out_size) {
    // Inputs: h [10000,128] f32, src [E] i32, dst [E] i32 (jax x64 disabled)
    const float4* h   = (const float4*)d_in[0];
    const int*    src = (const int*)d_in[1];
    const int*    dst = (const int*)d_in[2];
    float*        out = (float*)d_out;

    const int n_edges  = in_sizes[1];        // E = 640000
    const int n_groups = n_edges / 4;        // 160000 groups of 4 edges
    const int tail     = n_edges - n_groups * 4;

    if (n_groups > 0) {
        const int threads = 256;             // 8 warps -> 32 edges/block
        const int wpb = threads / 32;
        const int blocks = (n_groups + wpb - 1) / wpb;
        edge_dot4_kernel<<<blocks, threads>>>(h, (const int4*)src,
                                              (const int4*)dst,
                                              (float4*)out, n_groups);
    }
    if (tail > 0) {
        edge_dot_tail_kernel<<<1, 256>>>(h, src, dst, out,
                                         n_groups * 4, n_edges);
    }
}

// round 4
// speedup vs baseline: 1.6000x; 1.1021x over previous
#include <cuda_runtime.h>
#include <cstdint>

// Per-edge dot: out[e] = dot(h[src[e]], h[dst[e]]), D=128 fp32.
// 8 edges per warp:
//  - 2x int4 index loads per side (uniform broadcast)
//  - 16 independent warp-coalesced LDG.128 gathers (512B per vector)
//  - combined hierarchical reduction: 2 butterfly levels on all 8 sums,
//    then each 8-lane octet finishes 2 edges (22 SHFL per 8 edges)
//  - lanes {0,8,16,24} store float2 -> one coalesced 32B store wavefront.

__device__ __forceinline__ float dot4(float4 a, float4 b) {
    float s = a.x * b.x;
    s = fmaf(a.y, b.y, s);
    s = fmaf(a.z, b.z, s);
    s = fmaf(a.w, b.w, s);
    return s;
}

__device__ __forceinline__ float red2(float v) {   // xor16 + xor8
    v += __shfl_xor_sync(0xFFFFFFFFu, v, 16);
    v += __shfl_xor_sync(0xFFFFFFFFu, v, 8);
    return v;
}

__device__ __forceinline__ float red3(float v) {   // xor4 + xor2 + xor1
    v += __shfl_xor_sync(0xFFFFFFFFu, v, 4);
    v += __shfl_xor_sync(0xFFFFFFFFu, v, 2);
    v += __shfl_xor_sync(0xFFFFFFFFu, v, 1);
    return v;
}

__device__ __forceinline__ float warp_bfly_sum(float v) {
    #pragma unroll
    for (int off = 16; off > 0; off >>= 1)
        v += __shfl_xor_sync(0xFFFFFFFFu, v, off);
    return v;
}

__global__ __launch_bounds__(256)
void edge_dot8_kernel(const float4* __restrict__ h,
                      const int4* __restrict__ src4,
                      const int4* __restrict__ dst4,
                      float2* __restrict__ out2,
                      int n_groups) {
    const int g    = (blockIdx.x * blockDim.x + threadIdx.x) >> 5;
    const int lane = threadIdx.x & 31;
    if (g >= n_groups) return;

    // 8 src + 8 dst indices, uniform across warp
    const int4 s0 = __ldg(&src4[2 * g]);
    const int4 s1 = __ldg(&src4[2 * g + 1]);
    const int4 d0 = __ldg(&dst4[2 * g]);
    const int4 d1 = __ldg(&dst4[2 * g + 1]);

    // 16 independent gathers: one warp-wide LDG.128 = one 512B vector
    const float4 a0 = __ldg(&h[(long)s0.x * 32 + lane]);
    const float4 b0 = __ldg(&h[(long)d0.x * 32 + lane]);
    const float4 a1 = __ldg(&h[(long)s0.y * 32 + lane]);
    const float4 b1 = __ldg(&h[(long)d0.y * 32 + lane]);
    const float4 a2 = __ldg(&h[(long)s0.z * 32 + lane]);
    const float4 b2 = __ldg(&h[(long)d0.z * 32 + lane]);
    const float4 a3 = __ldg(&h[(long)s0.w * 32 + lane]);
    const float4 b3 = __ldg(&h[(long)d0.w * 32 + lane]);
    const float4 a4 = __ldg(&h[(long)s1.x * 32 + lane]);
    const float4 b4 = __ldg(&h[(long)d1.x * 32 + lane]);
    const float4 a5 = __ldg(&h[(long)s1.y * 32 + lane]);
    const float4 b5 = __ldg(&h[(long)d1.y * 32 + lane]);
    const float4 a6 = __ldg(&h[(long)s1.z * 32 + lane]);
    const float4 b6 = __ldg(&h[(long)d1.z * 32 + lane]);
    const float4 a7 = __ldg(&h[(long)s1.w * 32 + lane]);
    const float4 b7 = __ldg(&h[(long)d1.w * 32 + lane]);

    // Per-lane partial dots (edge i = 8g + i)
    float r0 = red2(dot4(a0, b0));
    float r1 = red2(dot4(a1, b1));
    float r2 = red2(dot4(a2, b2));
    float r3 = red2(dot4(a3, b3));
    float r4 = red2(dot4(a4, b4));
    float r5 = red2(dot4(a5, b5));
    float r6 = red2(dot4(a6, b6));
    float r7 = red2(dot4(a7, b7));

    // After xor16+xor8 the value at lane l depends only on (l & 7) and is
    // replicated across the 4 octets. Octet q finishes edges 2q and 2q+1.
    const int octet = lane >> 3;
    float va = (octet & 2) ? ((octet & 1) ? r6 : r4)
                           : ((octet & 1) ? r2 : r0);
    float vb = (octet & 2) ? ((octet & 1) ? r7 : r5)
                           : ((octet & 1) ? r3 : r1);
    va = red3(va);
    vb = red3(vb);

    // Edge 8g+2q -> out2[4g+q].x, edge 8g+2q+1 -> .y
    if ((lane & 7) == 0) out2[4 * g + octet] = make_float2(va, vb);
}

// Tail: one warp per edge (launched only when n_edges % 8 != 0)
__global__ void edge_dot_tail_kernel(const float4* __restrict__ h,
                                     const int* __restrict__ src,
                                     const int* __restrict__ dst,
                                     float* __restrict__ out,
                                     int base, int n_edges) {
    const int e    = base + ((blockIdx.x * blockDim.x + threadIdx.x) >> 5);
    const int lane = threadIdx.x & 31;
    if (e >= n_edges) return;
    const int s = __ldg(&src[e]);
    const int d = __ldg(&dst[e]);
    const float4 va = __ldg(&h[(long)s * 32 + lane]);
    const float4 vb = __ldg(&h[(long)d * 32 + lane]);
    float r = warp_bfly_sum(dot4(va, vb));
    if (lane == 0) out[e] = r;
}

extern "C" void kernel_launch(void* const* d_in, const int* in_sizes, int n_in,
                              void* d_out, int out_size) {
    // Inputs: h [10000,128] f32, src [E] i32, dst [E] i32 (jax x64 disabled)
    const float4* h   = (const float4*)d_in[0];
    const int*    src = (const int*)d_in[1];
    const int*    dst = (const int*)d_in[2];
    float*        out = (float*)d_out;

    const int n_edges  = in_sizes[1];        // E = 640000
    const int n_groups = n_edges / 8;        // 80000 groups of 8 edges
    const int tail     = n_edges - n_groups * 8;

    if (n_groups > 0) {
        const int threads = 256;             // 8 warps -> 64 edges/block
        const int wpb = threads / 32;
        const int blocks = (n_groups + wpb - 1) / wpb;
        edge_dot8_kernel<<<blocks, threads>>>(h, (const int4*)src,
                                              (const int4*)dst,
                                              (float2*)out, n_groups);
    }
    if (tail > 0) {
        edge_dot_tail_kernel<<<1, 256>>>(h, src, dst, out,
                                         n_groups * 8, n_edges);
    }
}

// round 6
// speedup vs baseline: 1.6110x; 1.0069x over previous
#include <cuda_runtime.h>
#include <cstdint>

// Per-edge dot: out[e] = dot(h[src[e]], h[dst[e]]), D=128 fp32.
// Persistent warps, 8 edges per warp-iteration, software-pipelined:
//  - steady state: next group's 4 int4 index loads are in flight while the
//    current group's gathers/reduction run (hides ~600cy index latency)
//  - 16 independent warp-coalesced LDG.128 gathers (512B per vector)
//  - combined reduction: xor16+xor8 on all 8 sums, then each 8-lane octet
//    finishes 2 edges (22 SHFL per 8 edges)
//  - lanes {0,8,16,24} store float2 -> one coalesced 32B wavefront.

__device__ __forceinline__ float dot4(float4 a, float4 b) {
    float s = a.x * b.x;
    s = fmaf(a.y, b.y, s);
    s = fmaf(a.z, b.z, s);
    s = fmaf(a.w, b.w, s);
    return s;
}

__device__ __forceinline__ float red2(float v) {   // xor16 + xor8
    v += __shfl_xor_sync(0xFFFFFFFFu, v, 16);
    v += __shfl_xor_sync(0xFFFFFFFFu, v, 8);
    return v;
}

__device__ __forceinline__ float red3(float v) {   // xor4 + xor2 + xor1
    v += __shfl_xor_sync(0xFFFFFFFFu, v, 4);
    v += __shfl_xor_sync(0xFFFFFFFFu, v, 2);
    v += __shfl_xor_sync(0xFFFFFFFFu, v, 1);
    return v;
}

__device__ __forceinline__ float warp_bfly_sum(float v) {
    #pragma unroll
    for (int off = 16; off > 0; off >>= 1)
        v += __shfl_xor_sync(0xFFFFFFFFu, v, off);
    return v;
}

__global__ __launch_bounds__(256)
void edge_dot8_pers_kernel(const float4* __restrict__ h,
                           const int4* __restrict__ src4,
                           const int4* __restrict__ dst4,
                           float2* __restrict__ out2,
                           int n_groups) {
    const int lane    = threadIdx.x & 31;
    const int octet   = lane >> 3;
    const int gwarp   = (blockIdx.x * blockDim.x + threadIdx.x) >> 5;
    const int n_warps = (gridDim.x * blockDim.x) >> 5;

    int g = gwarp;
    if (g >= n_groups) return;

    // Prologue: load first group's indices
    int4 s0 = __ldg(&src4[2 * g]);
    int4 s1 = __ldg(&src4[2 * g + 1]);
    int4 d0 = __ldg(&dst4[2 * g]);
    int4 d1 = __ldg(&dst4[2 * g + 1]);

    while (true) {
        // Issue all 16 gathers for the current group first (max MLP)
        const float4 a0 = __ldg(&h[(long)s0.x * 32 + lane]);
        const float4 b0 = __ldg(&h[(long)d0.x * 32 + lane]);
        const float4 a1 = __ldg(&h[(long)s0.y * 32 + lane]);
        const float4 b1 = __ldg(&h[(long)d0.y * 32 + lane]);
        const float4 a2 = __ldg(&h[(long)s0.z * 32 + lane]);
        const float4 b2 = __ldg(&h[(long)d0.z * 32 + lane]);
        const float4 a3 = __ldg(&h[(long)s0.w * 32 + lane]);
        const float4 b3 = __ldg(&h[(long)d0.w * 32 + lane]);
        const float4 a4 = __ldg(&h[(long)s1.x * 32 + lane]);
        const float4 b4 = __ldg(&h[(long)d1.x * 32 + lane]);
        const float4 a5 = __ldg(&h[(long)s1.y * 32 + lane]);
        const float4 b5 = __ldg(&h[(long)d1.y * 32 + lane]);
        const float4 a6 = __ldg(&h[(long)s1.z * 32 + lane]);
        const float4 b6 = __ldg(&h[(long)d1.z * 32 + lane]);
        const float4 a7 = __ldg(&h[(long)s1.w * 32 + lane]);
        const float4 b7 = __ldg(&h[(long)d1.w * 32 + lane]);

        // Prefetch next group's indices while gathers are in flight
        const int gn = g + n_warps;
        const bool more = (gn < n_groups);
        int4 ns0, ns1, nd0, nd1;
        if (more) {
            ns0 = __ldg(&src4[2 * gn]);
            ns1 = __ldg(&src4[2 * gn + 1]);
            nd0 = __ldg(&dst4[2 * gn]);
            nd1 = __ldg(&dst4[2 * gn + 1]);
        }

        // Partial dots + first two butterfly levels
        float r0 = red2(dot4(a0, b0));
        float r1 = red2(dot4(a1, b1));
        float r2 = red2(dot4(a2, b2));
        float r3 = red2(dot4(a3, b3));
        float r4 = red2(dot4(a4, b4));
        float r5 = red2(dot4(a5, b5));
        float r6 = red2(dot4(a6, b6));
        float r7 = red2(dot4(a7, b7));

        // After xor16+xor8, value at lane l depends only on (l & 7),
        // replicated across the 4 octets. Octet q finishes edges 2q, 2q+1.
        float va = (octet & 2) ? ((octet & 1) ? r6 : r4)
                               : ((octet & 1) ? r2 : r0);
        float vb = (octet & 2) ? ((octet & 1) ? r7 : r5)
                               : ((octet & 1) ? r3 : r1);
        va = red3(va);
        vb = red3(vb);

        if ((lane & 7) == 0) out2[4 * g + octet] = make_float2(va, vb);

        if (!more) break;
        s0 = ns0; s1 = ns1; d0 = nd0; d1 = nd1;
        g = gn;
    }
}

// Tail: one warp per edge (launched only when n_edges % 8 != 0)
__global__ void edge_dot_tail_kernel(const float4* __restrict__ h,
                                     const int* __restrict__ src,
                                     const int* __restrict__ dst,
                                     float* __restrict__ out,
                                     int base, int n_edges) {
    const int e    = base + ((blockIdx.x * blockDim.x + threadIdx.x) >> 5);
    const int lane = threadIdx.x & 31;
    if (e >= n_edges) return;
    const int s = __ldg(&src[e]);
    const int d = __ldg(&dst[e]);
    const float4 va = __ldg(&h[(long)s * 32 + lane]);
    const float4 vb = __ldg(&h[(long)d * 32 + lane]);
    float r = warp_bfly_sum(dot4(va, vb));
    if (lane == 0) out[e] = r;
}

extern "C" void kernel_launch(void* const* d_in, const int* in_sizes, int n_in,
                              void* d_out, int out_size) {
    // Inputs: h [10000,128] f32, src [E] i32, dst [E] i32 (jax x64 disabled)
    const float4* h   = (const float4*)d_in[0];
    const int*    src = (const int*)d_in[1];
    const int*    dst = (const int*)d_in[2];
    float*        out = (float*)d_out;

    const int n_edges  = in_sizes[1];        // E = 640000
    const int n_groups = n_edges / 8;        // 80000 groups of 8 edges
    const int tail     = n_edges - n_groups * 8;

    if (n_groups > 0) {
        const int threads = 256;             // 8 warps per block
        // Persistent-style grid: ~4 blocks per SM on 148 SMs
        int blocks = 148 * 4;
        const int wpb = threads / 32;
        const int max_blocks = (n_groups + wpb - 1) / wpb;
        if (blocks > max_blocks) blocks = max_blocks;
        edge_dot8_pers_kernel<<<blocks, threads>>>(h, (const int4*)src,
                                                   (const int4*)dst,
                                                   (float2*)out, n_groups);
    }
    if (tail > 0) {
        edge_dot_tail_kernel<<<1, 256>>>(h, src, dst, out,
                                         n_groups * 8, n_edges);
    }
}